// round 13
// baseline (speedup 1.0000x reference)
#include <cuda_runtime.h>
#include <cuda_bf16.h>
#include <cuda_fp16.h>
#include <cstdint>

#define N_NODES 50000
#define N_EDGES 600000
#define D_IN    256
#define D_OUT   128

// ---------------- scratch (static device globals; no allocation) ----------------
__device__ __half g_E [N_NODES * D_IN];    // gathered embed, fp16
__device__ __half g_xh[N_NODES * D_OUT];   // gemm1 out (prescaled*256, fp16)
__device__ __half g_hh[N_NODES * D_OUT];   // gemm2 out (relu, prescaled*256, fp16)
__device__ __half g_Wnh[128 * D_IN],  g_Wnl[128 * D_IN];
__device__ __half g_w1h[128 * D_OUT], g_w1l[128 * D_OUT];
__device__ __half g_w2h[128 * D_OUT], g_w2l[128 * D_OUT];

__device__ float g_dinv[N_NODES];
__device__ int   g_deg [N_NODES];
__device__ int   g_cur [N_NODES];
__device__ int   g_off [N_NODES + 1];
__device__ int   g_bsum [256];
__device__ int   g_csr [N_EDGES];

// ---------------- helpers ----------------
__device__ __forceinline__ void wsplit2(float x, float y, uint32_t& hi, uint32_t& lo) {
    __half2 h = __floats2half2_rn(x, y);
    float2 hf = __half22float2(h);
    __half2 l = __floats2half2_rn(x - hf.x, y - hf.y);
    hi = *(uint32_t*)&h; lo = *(uint32_t*)&l;
}
__device__ __forceinline__ void cp_async16(uint32_t saddr, const void* gaddr) {
    asm volatile("cp.async.cg.shared.global [%0], [%1], 16;" :: "r"(saddr), "l"(gaddr));
}
__device__ __forceinline__ void cp_commit() {
    asm volatile("cp.async.commit_group;" ::: "memory");
}
template<int N> __device__ __forceinline__ void cp_wait() {
    asm volatile("cp.async.wait_group %0;" :: "n"(N) : "memory");
}
__device__ __forceinline__ void mma16816h(float* d, uint32_t a0, uint32_t a1,
                                          uint32_t a2, uint32_t a3,
                                          uint32_t b0, uint32_t b1) {
    asm volatile(
        "mma.sync.aligned.m16n8k16.row.col.f32.f16.f16.f32 "
        "{%0,%1,%2,%3}, {%4,%5,%6,%7}, {%8,%9}, {%0,%1,%2,%3};"
        : "+f"(d[0]), "+f"(d[1]), "+f"(d[2]), "+f"(d[3])
        : "r"(a0), "r"(a1), "r"(a2), "r"(a3), "r"(b0), "r"(b1));
}
__device__ __forceinline__ void hacc(float* a, uint2 v) {
    float2 p0 = __half22float2(*(__half2*)&v.x);
    float2 p1 = __half22float2(*(__half2*)&v.y);
    a[0] += p0.x; a[1] += p0.y; a[2] += p1.x; a[3] += p1.y;
}

// ---------------- merged prep: gather embed -> fp16, plus weight splitting ----------------
__global__ void k_prep(const float* __restrict__ embed, const int* __restrict__ tokens,
                       const float* __restrict__ Wn, const float* __restrict__ w1,
                       const float* __restrict__ w2, int nbp) {
    if ((int)blockIdx.x >= nbp) {
        int i = (blockIdx.x - nbp) * 256 + threadIdx.x;
        const float* s; __half *ph, *pl; int off;
        if (i < 8192)       { s = Wn; ph = g_Wnh; pl = g_Wnl; off = i; }
        else if (i < 12288) { s = w1; ph = g_w1h; pl = g_w1l; off = i - 8192; }
        else                { s = w2; ph = g_w2h; pl = g_w2l; off = i - 12288; }
        float4 v = ((const float4*)s)[off];
        uint2 hi, lo;
        wsplit2(v.x, v.y, hi.x, lo.x);
        wsplit2(v.z, v.w, hi.y, lo.y);
        ((uint2*)ph)[off] = hi; ((uint2*)pl)[off] = lo;
        return;
    }
    int t = blockIdx.x * 256 + threadIdx.x;
    if (t >= N_NODES * (D_IN / 4)) return;
    int row = t >> 6, q = t & 63;
    int tok = __ldg(&tokens[row]);
    float4 v = ((const float4*)embed)[(size_t)tok * (D_IN / 4) + q];
    __half2 a = __floats2half2_rn(v.x, v.y);
    __half2 b = __floats2half2_rn(v.z, v.w);
    uint2 o = { *(uint32_t*)&a, *(uint32_t*)&b };
    ((uint2*)g_E)[(size_t)row * (D_IN / 4) + q] = o;
}

// ---------------- graph-structure kernels ----------------
__global__ void k_zero() {
    int i = blockIdx.x * blockDim.x + threadIdx.x;
    if (i < N_NODES) g_deg[i] = 0;
}
__global__ void k_count(const int* __restrict__ dst) {
    int t = blockIdx.x * blockDim.x + threadIdx.x;
    if (t * 4 >= N_EDGES) return;
    int4 d = ((const int4*)dst)[t];
    atomicAdd(&g_deg[d.x], 1); atomicAdd(&g_deg[d.y], 1);
    atomicAdd(&g_deg[d.z], 1); atomicAdd(&g_deg[d.w], 1);
}
__global__ void k_scan1() {
    __shared__ int s[256];
    int i = blockIdx.x * 256 + threadIdx.x;
    int v = (i < N_NODES) ? g_deg[i] : 0;
    if (i < N_NODES) g_dinv[i] = rsqrtf((float)(v + 1));
    s[threadIdx.x] = v; __syncthreads();
    for (int d = 128; d > 0; d >>= 1) {
        if (threadIdx.x < d) s[threadIdx.x] += s[threadIdx.x + d];
        __syncthreads();
    }
    if (threadIdx.x == 0) g_bsum[blockIdx.x] = s[0];
}
__global__ void k_scan23() {
    __shared__ int bs[256];
    __shared__ int s[256];
    int t = threadIdx.x;
    int nblk = gridDim.x;
    int bv = (t < nblk) ? g_bsum[t] : 0;
    bs[t] = bv; __syncthreads();
    for (int d = 1; d < 256; d <<= 1) {
        int u = (t >= d) ? bs[t - d] : 0;
        __syncthreads(); bs[t] += u; __syncthreads();
    }
    int base = blockIdx.x ? bs[blockIdx.x - 1] : 0;
    int i = blockIdx.x * 256 + t;
    int v = (i < N_NODES) ? g_deg[i] : 0;
    s[t] = v; __syncthreads();
    for (int d = 1; d < 256; d <<= 1) {
        int u = (t >= d) ? s[t - d] : 0;
        __syncthreads(); s[t] += u; __syncthreads();
    }
    if (i < N_NODES) { g_off[i] = base + s[t] - v; g_cur[i] = 0; }
    if (i == 0) g_off[N_NODES] = N_EDGES;
}
__global__ void k_fill(const int* __restrict__ src, const int* __restrict__ dst) {
    int t = blockIdx.x * blockDim.x + threadIdx.x;
    if (t * 4 >= N_EDGES) return;
    int4 d = ((const int4*)dst)[t];
    int4 s = ((const int4*)src)[t];
    int p0 = g_off[d.x] + atomicAdd(&g_cur[d.x], 1);
    int p1 = g_off[d.y] + atomicAdd(&g_cur[d.y], 1);
    int p2 = g_off[d.z] + atomicAdd(&g_cur[d.z], 1);
    int p3 = g_off[d.w] + atomicAdd(&g_cur[d.w], 1);
    g_csr[p0] = s.x; g_csr[p1] = s.y; g_csr[p2] = s.z; g_csr[p3] = s.w;
}

// ---------------- GEMM1: cp.async double-buffered (A from gmem, K=256) ----------------
#define SROWW 20
#define STAGE_W   (3 * 128 * SROWW)
#define STAGE_B   (STAGE_W * 4)
#define SMEM_DYN  (2 * STAGE_B)            // 61440 B

__global__ void __launch_bounds__(256)
k_gemm1(const __half* __restrict__ A,
        const __half* __restrict__ Whi, const __half* __restrict__ Wlo,
        const float* __restrict__ bias, __half* __restrict__ Oh)
{
    extern __shared__ __align__(16) char smem_dyn[];
    uint32_t* S = (uint32_t*)smem_dyn;
    const uint32_t sbase = (uint32_t)__cvta_generic_to_shared(smem_dyn);

    const int tid  = threadIdx.x;
    const int wid  = tid >> 5;
    const int lane = tid & 31;
    const int m_base = (wid >> 1) * 32;
    const int n_base = (wid & 1) * 64;
    const int n0   = blockIdx.x * 128;
    const int qr = lane >> 2;
    const int qj = lane & 3;
    constexpr int K = D_IN, NCH = K / 32;

    auto issue = [&](int c, int buf) {
        #pragma unroll
        for (int it = 0; it < 6; it++) {
            int i     = it * 256 + tid;
            int plane = i >> 9;
            int r     = (i >> 2) & 127;
            int q     = i & 3;
            const __half* P = (plane == 0) ? A : (plane == 1) ? Whi : Wlo;
            int rg;
            if (plane == 0) { int node = n0 + r; if (node >= N_NODES) node = N_NODES - 1; rg = node; }
            else            rg = r;
            const char* src = (const char*)P + ((size_t)rg * K + c * 32 + q * 8) * 2;
            uint32_t dstb = sbase + buf * STAGE_B + plane * (128 * SROWW * 4)
                          + r * (SROWW * 4) + q * 16;
            cp_async16(dstb, src);
        }
        cp_commit();
    };

    float acc[2][8][4];
    #pragma unroll
    for (int mt = 0; mt < 2; mt++)
        #pragma unroll
        for (int nt = 0; nt < 8; nt++)
            #pragma unroll
            for (int q = 0; q < 4; q++) acc[mt][nt][q] = 0.f;

    issue(0, 0);
    issue(1, 1);

    #pragma unroll
    for (int c = 0; c < NCH; c++) {
        if (c + 1 < NCH) cp_wait<1>(); else cp_wait<0>();
        __syncthreads();
        const int bw = (c & 1) * STAGE_W;
        uint32_t* sA  = S + bw;
        uint32_t* sWh = S + bw + 128 * SROWW;
        uint32_t* sWl = S + bw + 2 * 128 * SROWW;
        #pragma unroll
        for (int ks = 0; ks < 2; ks++) {
            const int kw = ks * 8 + qj;
            uint32_t a[2][4];
            #pragma unroll
            for (int mt = 0; mt < 2; mt++) {
                int r0 = (m_base + mt * 16 + qr) * SROWW;
                int r1 = (m_base + mt * 16 + qr + 8) * SROWW;
                a[mt][0] = sA[r0 + kw];     a[mt][1] = sA[r1 + kw];
                a[mt][2] = sA[r0 + kw + 4]; a[mt][3] = sA[r1 + kw + 4];
            }
            #pragma unroll
            for (int nt = 0; nt < 8; nt++) {
                int nr = (n_base + nt * 8 + qr) * SROWW;
                uint32_t bh0 = sWh[nr + kw], bh1 = sWh[nr + kw + 4];
                uint32_t bl0 = sWl[nr + kw], bl1 = sWl[nr + kw + 4];
                #pragma unroll
                for (int mt = 0; mt < 2; mt++) {
                    mma16816h(acc[mt][nt], a[mt][0], a[mt][1], a[mt][2], a[mt][3], bh0, bh1);
                    mma16816h(acc[mt][nt], a[mt][0], a[mt][1], a[mt][2], a[mt][3], bl0, bl1);
                }
            }
        }
        __syncthreads();
        if (c + 2 < NCH) issue(c + 2, c & 1);
    }

    // epilogue: +bias, *dinv*256, fp16 out
    #pragma unroll
    for (int mt = 0; mt < 2; mt++) {
        int r0 = n0 + m_base + mt * 16 + qr;
        int r1 = r0 + 8;
        float d0 = (r0 < N_NODES) ? g_dinv[r0] * 256.f : 0.f;
        float d1 = (r1 < N_NODES) ? g_dinv[r1] * 256.f : 0.f;
        #pragma unroll
        for (int nt = 0; nt < 8; nt++) {
            int col = n_base + nt * 8 + qj * 2;
            float b0 = bias[col], b1 = bias[col + 1];
            if (r0 < N_NODES) {
                __half2 h = __floats2half2_rn((acc[mt][nt][0] + b0) * d0, (acc[mt][nt][1] + b1) * d0);
                ((uint32_t*)Oh)[(size_t)r0 * 64 + (col >> 1)] = *(uint32_t*)&h;
            }
            if (r1 < N_NODES) {
                __half2 h = __floats2half2_rn((acc[mt][nt][2] + b0) * d1, (acc[mt][nt][3] + b1) * d1);
                ((uint32_t*)Oh)[(size_t)r1 * 64 + (col >> 1)] = *(uint32_t*)&h;
            }
        }
    }
}

// ---------------- fused agg + GEMM (K=128): phase1 agg -> smem Z, phase2 MMA ----------------
// Z[n] = (dinv[n]/256) * sum_{s in n ∪ in(n)} x[s]  (x prescaled by dinv*256)
// out = Z @ W^T + bias [relu] [*dinv*256 -> fp16] or fp32
#define ZROWW  68                                 // Z tile row stride (u32)
#define ZTILE_B   (128 * ZROWW * 4)               // 34816 B
#define WPLANE_B  (128 * SROWW * 4)               // 10240 B
#define WSTAGE_B  (2 * WPLANE_B)                  // 20480 B
#define SMEM_FUSE (ZTILE_B + 2 * WSTAGE_B)        // 75776 B

template<bool RELU_OUT, bool HALF_OUT, bool SCALE>
__global__ void __launch_bounds__(256)
k_aggemm(const __half* __restrict__ x,
         const __half* __restrict__ Whi, const __half* __restrict__ Wlo,
         const float* __restrict__ bias, __half* __restrict__ Oh, float* __restrict__ Of)
{
    extern __shared__ __align__(16) char smem_dyn[];
    uint32_t* sZ = (uint32_t*)smem_dyn;
    uint32_t* SW = (uint32_t*)(smem_dyn + ZTILE_B);
    const uint32_t sbase = (uint32_t)__cvta_generic_to_shared(smem_dyn);

    const int tid  = threadIdx.x;
    const int wid  = tid >> 5;
    const int lane = tid & 31;
    const int m_base = (wid >> 1) * 32;
    const int n_base = (wid & 1) * 64;
    const int n0   = blockIdx.x * 128;
    const int qr = lane >> 2;
    const int qj = lane & 3;
    constexpr int K = D_OUT, NCH = K / 32;        // 4 chunks

    auto issueW = [&](int c, int buf) {
        #pragma unroll
        for (int it = 0; it < 4; it++) {          // 2 planes x 128 rows x 4 uint4 = 1024
            int i     = it * 256 + tid;
            int plane = i >> 9;
            int r     = (i >> 2) & 127;
            int q     = i & 3;
            const __half* P = plane ? Wlo : Whi;
            const char* src = (const char*)P + ((size_t)r * K + c * 32 + q * 8) * 2;
            uint32_t dstb = sbase + ZTILE_B + buf * WSTAGE_B + plane * WPLANE_B
                          + r * (SROWW * 4) + q * 16;
            cp_async16(dstb, src);
        }
        cp_commit();
    };

    // prefetch W chunks 0,1 before aggregation (rides under the gather)
    issueW(0, 0);
    issueW(1, 1);

    // ---- phase 1: aggregate 16 nodes per warp into smem Z tile ----
    const uint2* x4 = (const uint2*)x;
    for (int i = 0; i < 16; i++) {
        int node = n0 + wid * 16 + i;
        float a[4] = {0.f, 0.f, 0.f, 0.f};
        if (node < N_NODES) {
            hacc(a, x4[(size_t)node * 32 + lane]);      // self
            int b = g_off[node], e = g_off[node + 1];
            int j = b;
            for (; j + 4 <= e; j += 4) {
                int s0 = g_csr[j], s1 = g_csr[j+1], s2 = g_csr[j+2], s3 = g_csr[j+3];
                uint2 v0 = x4[(size_t)s0 * 32 + lane];
                uint2 v1 = x4[(size_t)s1 * 32 + lane];
                uint2 v2 = x4[(size_t)s2 * 32 + lane];
                uint2 v3 = x4[(size_t)s3 * 32 + lane];
                hacc(a, v0); hacc(a, v1); hacc(a, v2); hacc(a, v3);
            }
            for (; j < e; j++) hacc(a, x4[(size_t)g_csr[j] * 32 + lane]);
            float di = g_dinv[node] * (1.f / 256.f);
            a[0] *= di; a[1] *= di; a[2] *= di; a[3] *= di;
        }
        __half2 o0 = __floats2half2_rn(a[0], a[1]);
        __half2 o1 = __floats2half2_rn(a[2], a[3]);
        uint2 o = { *(uint32_t*)&o0, *(uint32_t*)&o1 };
        *(uint2*)&sZ[(wid * 16 + i) * ZROWW + lane * 2] = o;
    }

    // ---- phase 2: MMA with A from smem Z ----
    float acc[2][8][4];
    #pragma unroll
    for (int mt = 0; mt < 2; mt++)
        #pragma unroll
        for (int nt = 0; nt < 8; nt++)
            #pragma unroll
            for (int q = 0; q < 4; q++) acc[mt][nt][q] = 0.f;

    #pragma unroll
    for (int c = 0; c < NCH; c++) {
        if (c + 1 < NCH) cp_wait<1>(); else cp_wait<0>();
        __syncthreads();
        uint32_t* sWh = SW + (c & 1) * (WSTAGE_B / 4);
        uint32_t* sWl = sWh + (WPLANE_B / 4);
        const int cb = c * 16;
        #pragma unroll
        for (int ks = 0; ks < 2; ks++) {
            const int kw = ks * 8 + qj;
            uint32_t a[2][4];
            #pragma unroll
            for (int mt = 0; mt < 2; mt++) {
                int r0 = (m_base + mt * 16 + qr) * ZROWW + cb;
                int r1 = (m_base + mt * 16 + qr + 8) * ZROWW + cb;
                a[mt][0] = sZ[r0 + kw];     a[mt][1] = sZ[r1 + kw];
                a[mt][2] = sZ[r0 + kw + 4]; a[mt][3] = sZ[r1 + kw + 4];
            }
            #pragma unroll
            for (int nt = 0; nt < 8; nt++) {
                int nr = (n_base + nt * 8 + qr) * SROWW;
                uint32_t bh0 = sWh[nr + kw], bh1 = sWh[nr + kw + 4];
                uint32_t bl0 = sWl[nr + kw], bl1 = sWl[nr + kw + 4];
                #pragma unroll
                for (int mt = 0; mt < 2; mt++) {
                    mma16816h(acc[mt][nt], a[mt][0], a[mt][1], a[mt][2], a[mt][3], bh0, bh1);
                    mma16816h(acc[mt][nt], a[mt][0], a[mt][1], a[mt][2], a[mt][3], bl0, bl1);
                }
            }
        }
        __syncthreads();
        if (c + 2 < NCH) issueW(c + 2, c & 1);
    }

    // ---- epilogue ----
    #pragma unroll
    for (int mt = 0; mt < 2; mt++) {
        int r0 = n0 + m_base + mt * 16 + qr;
        int r1 = r0 + 8;
        float d0 = 1.f, d1 = 1.f;
        if (SCALE) {
            d0 = (r0 < N_NODES) ? g_dinv[r0] * 256.f : 0.f;
            d1 = (r1 < N_NODES) ? g_dinv[r1] * 256.f : 0.f;
        }
        #pragma unroll
        for (int nt = 0; nt < 8; nt++) {
            int col = n_base + nt * 8 + qj * 2;
            float b0 = bias[col], b1 = bias[col + 1];
            float vx0 = acc[mt][nt][0] + b0, vy0 = acc[mt][nt][1] + b1;
            float vx1 = acc[mt][nt][2] + b0, vy1 = acc[mt][nt][3] + b1;
            if (RELU_OUT) {
                vx0 = fmaxf(vx0, 0.f); vy0 = fmaxf(vy0, 0.f);
                vx1 = fmaxf(vx1, 0.f); vy1 = fmaxf(vy1, 0.f);
            }
            if (SCALE) { vx0 *= d0; vy0 *= d0; vx1 *= d1; vy1 *= d1; }
            if (HALF_OUT) {
                if (r0 < N_NODES) {
                    __half2 h = __floats2half2_rn(vx0, vy0);
                    ((uint32_t*)Oh)[(size_t)r0 * 64 + (col >> 1)] = *(uint32_t*)&h;
                }
                if (r1 < N_NODES) {
                    __half2 h = __floats2half2_rn(vx1, vy1);
                    ((uint32_t*)Oh)[(size_t)r1 * 64 + (col >> 1)] = *(uint32_t*)&h;
                }
            } else {
                if (r0 < N_NODES)
                    *(float2*)(Of + (size_t)r0 * D_OUT + col) = make_float2(vx0, vy0);
                if (r1 < N_NODES)
                    *(float2*)(Of + (size_t)r1 * D_OUT + col) = make_float2(vx1, vy1);
            }
        }
    }
}

// ---------------- launch ----------------
extern "C" void kernel_launch(void* const* d_in, const int* in_sizes, int n_in,
                              void* d_out, int out_size)
{
    const int*   tokens = (const int*)  d_in[0];
    const int*   eidx   = (const int*)  d_in[1];
    const float* embed  = (const float*)d_in[2];
    const float* Wn     = (const float*)d_in[3];
    const float* Wb     = (const float*)d_in[4];
    const float* w1     = (const float*)d_in[5];
    const float* b1     = (const float*)d_in[6];
    const float* w2     = (const float*)d_in[7];
    const float* b2     = (const float*)d_in[8];
    float* out = (float*)d_out;

    const int* src = eidx;
    const int* dst = eidx + N_EDGES;

    __half *E, *xh, *hh, *Wnh, *Wnl, *w1h, *w1l, *w2h, *w2l;
    cudaGetSymbolAddress((void**)&E,   g_E);
    cudaGetSymbolAddress((void**)&xh,  g_xh);  cudaGetSymbolAddress((void**)&hh,  g_hh);
    cudaGetSymbolAddress((void**)&Wnh, g_Wnh); cudaGetSymbolAddress((void**)&Wnl, g_Wnl);
    cudaGetSymbolAddress((void**)&w1h, g_w1h); cudaGetSymbolAddress((void**)&w1l, g_w1l);
    cudaGetSymbolAddress((void**)&w2h, g_w2h); cudaGetSymbolAddress((void**)&w2l, g_w2l);

    cudaFuncSetAttribute(k_gemm1, cudaFuncAttributeMaxDynamicSharedMemorySize, SMEM_DYN);
    cudaFuncSetAttribute(k_aggemm<true,  true,  true >, cudaFuncAttributeMaxDynamicSharedMemorySize, SMEM_FUSE);
    cudaFuncSetAttribute(k_aggemm<false, false, false>, cudaFuncAttributeMaxDynamicSharedMemorySize, SMEM_FUSE);

    static cudaStream_t sB = nullptr;
    static cudaEvent_t evFork = nullptr, evDinv = nullptr, evCsr = nullptr;
    if (!sB) {
        cudaStreamCreateWithFlags(&sB, cudaStreamNonBlocking);
        cudaEventCreateWithFlags(&evFork, cudaEventDisableTiming);
        cudaEventCreateWithFlags(&evDinv, cudaEventDisableTiming);
        cudaEventCreateWithFlags(&evCsr,  cudaEventDisableTiming);
    }

    const int NB_N  = (N_NODES + 255) / 256;
    const int NB_E4 = (N_EDGES / 4 + 255) / 256;
    const int NB_G  = (N_NODES + 127) / 128;
    const int NB_P  = (N_NODES * (D_IN / 4) + 255) / 256;

    // fork
    cudaEventRecord(evFork, 0);
    cudaStreamWaitEvent(sB, evFork, 0);

    // stream B: graph structure
    k_zero  <<<NB_N,  256, 0, sB>>>();
    k_count <<<NB_E4, 256, 0, sB>>>(dst);
    k_scan1 <<<NB_N,  256, 0, sB>>>();
    cudaEventRecord(evDinv, sB);               // dinv ready
    k_scan23<<<NB_N,  256, 0, sB>>>();
    k_fill  <<<NB_E4, 256, 0, sB>>>(src, dst);
    cudaEventRecord(evCsr, sB);                // CSR ready

    // stream 0: prep, then GEMM1 (needs dinv for epilogue scale)
    k_prep<<<NB_P + 64, 256>>>(embed, tokens, Wn, w1, w2, NB_P);
    cudaStreamWaitEvent(0, evDinv, 0);
    k_gemm1<<<NB_G, 256, SMEM_DYN>>>(E, Wnh, Wnl, Wb, xh);

    // fused agg1+GEMM2 (needs CSR): hh = relu(agg(xh) @ w1^T + b1) * dinv*256
    cudaStreamWaitEvent(0, evCsr, 0);
    k_aggemm<true, true, true><<<NB_G, 256, SMEM_FUSE>>>(xh, w1h, w1l, b1, hh, nullptr);
    // fused agg2+GEMM3: out = agg(hh) @ w2^T + b2
    k_aggemm<false, false, false><<<NB_G, 256, SMEM_FUSE>>>(hh, w2h, w2l, b2, nullptr, out);
}

// round 14
// speedup vs baseline: 1.6076x; 1.6076x over previous
#include <cuda_runtime.h>
#include <cuda_bf16.h>
#include <cuda_fp16.h>
#include <cstdint>

#define N_NODES 50000
#define N_EDGES 600000
#define D_IN    256
#define D_OUT   128

// ---------------- scratch (static device globals; no allocation) ----------------
__device__ __half g_Z [N_NODES * D_OUT];   // agg output, fp16
__device__ __half g_xh[N_NODES * D_OUT];   // gemm1 out (prescaled*256, fp16)
__device__ __half g_hh[N_NODES * D_OUT];   // gemm2 out (relu, prescaled*256, fp16)
__device__ __half g_Wnh[128 * D_IN],  g_Wnl[128 * D_IN];
__device__ __half g_w1h[128 * D_OUT], g_w1l[128 * D_OUT];
__device__ __half g_w2h[128 * D_OUT], g_w2l[128 * D_OUT];

__device__ float g_dinv[N_NODES];
__device__ int   g_deg [N_NODES];
__device__ int   g_cur [N_NODES];
__device__ int   g_off [N_NODES + 1];
__device__ int   g_bsum [256];
__device__ int   g_csr [N_EDGES];

// ---------------- helpers ----------------
__device__ __forceinline__ void wsplit2(float x, float y, uint32_t& hi, uint32_t& lo) {
    __half2 h = __floats2half2_rn(x, y);
    float2 hf = __half22float2(h);
    __half2 l = __floats2half2_rn(x - hf.x, y - hf.y);
    hi = *(uint32_t*)&h; lo = *(uint32_t*)&l;
}
__device__ __forceinline__ void cp_async16(uint32_t saddr, const void* gaddr) {
    asm volatile("cp.async.cg.shared.global [%0], [%1], 16;" :: "r"(saddr), "l"(gaddr));
}
__device__ __forceinline__ void cp_commit() {
    asm volatile("cp.async.commit_group;" ::: "memory");
}
template<int N> __device__ __forceinline__ void cp_wait() {
    asm volatile("cp.async.wait_group %0;" :: "n"(N) : "memory");
}
__device__ __forceinline__ void mma16816h(float* d, uint32_t a0, uint32_t a1,
                                          uint32_t a2, uint32_t a3,
                                          uint32_t b0, uint32_t b1) {
    asm volatile(
        "mma.sync.aligned.m16n8k16.row.col.f32.f16.f16.f32 "
        "{%0,%1,%2,%3}, {%4,%5,%6,%7}, {%8,%9}, {%0,%1,%2,%3};"
        : "+f"(d[0]), "+f"(d[1]), "+f"(d[2]), "+f"(d[3])
        : "r"(a0), "r"(a1), "r"(a2), "r"(a3), "r"(b0), "r"(b1));
}
__device__ __forceinline__ void hacc(float* a, uint2 v) {
    float2 p0 = __half22float2(*(__half2*)&v.x);
    float2 p1 = __half22float2(*(__half2*)&v.y);
    a[0] += p0.x; a[1] += p0.y; a[2] += p1.x; a[3] += p1.y;
}
__device__ __forceinline__ uint32_t packh2(float x, float y) {
    __half2 h = __floats2half2_rn(x, y);
    return *(uint32_t*)&h;
}

// ---------------- weight split (runs on stream B, hidden) ----------------
__global__ void k_splitw(const float* __restrict__ Wn, const float* __restrict__ w1,
                         const float* __restrict__ w2) {
    int i = blockIdx.x * 256 + threadIdx.x;
    const float* s; __half *ph, *pl; int off;
    if (i < 8192)       { s = Wn; ph = g_Wnh; pl = g_Wnl; off = i; }
    else if (i < 12288) { s = w1; ph = g_w1h; pl = g_w1l; off = i - 8192; }
    else                { s = w2; ph = g_w2h; pl = g_w2l; off = i - 12288; }
    float4 v = ((const float4*)s)[off];
    uint2 hi, lo;
    wsplit2(v.x, v.y, hi.x, lo.x);
    wsplit2(v.z, v.w, hi.y, lo.y);
    ((uint2*)ph)[off] = hi; ((uint2*)pl)[off] = lo;
}

// ---------------- graph-structure kernels ----------------
__global__ void k_zero() {
    int i = blockIdx.x * blockDim.x + threadIdx.x;
    if (i < N_NODES) g_deg[i] = 0;
}
__global__ void k_count(const int* __restrict__ dst) {
    int t = blockIdx.x * blockDim.x + threadIdx.x;
    if (t * 4 >= N_EDGES) return;
    int4 d = ((const int4*)dst)[t];
    atomicAdd(&g_deg[d.x], 1); atomicAdd(&g_deg[d.y], 1);
    atomicAdd(&g_deg[d.z], 1); atomicAdd(&g_deg[d.w], 1);
}
__global__ void k_scan1() {
    __shared__ int s[256];
    int i = blockIdx.x * 256 + threadIdx.x;
    int v = (i < N_NODES) ? g_deg[i] : 0;
    if (i < N_NODES) g_dinv[i] = rsqrtf((float)(v + 1));
    s[threadIdx.x] = v; __syncthreads();
    for (int d = 128; d > 0; d >>= 1) {
        if (threadIdx.x < d) s[threadIdx.x] += s[threadIdx.x + d];
        __syncthreads();
    }
    if (threadIdx.x == 0) g_bsum[blockIdx.x] = s[0];
}
__global__ void k_scan23() {
    __shared__ int bs[256];
    __shared__ int s[256];
    int t = threadIdx.x;
    int nblk = gridDim.x;
    int bv = (t < nblk) ? g_bsum[t] : 0;
    bs[t] = bv; __syncthreads();
    for (int d = 1; d < 256; d <<= 1) {
        int u = (t >= d) ? bs[t - d] : 0;
        __syncthreads(); bs[t] += u; __syncthreads();
    }
    int base = blockIdx.x ? bs[blockIdx.x - 1] : 0;
    int i = blockIdx.x * 256 + t;
    int v = (i < N_NODES) ? g_deg[i] : 0;
    s[t] = v; __syncthreads();
    for (int d = 1; d < 256; d <<= 1) {
        int u = (t >= d) ? s[t - d] : 0;
        __syncthreads(); s[t] += u; __syncthreads();
    }
    if (i < N_NODES) { g_off[i] = base + s[t] - v; g_cur[i] = 0; }
    if (i == 0) g_off[N_NODES] = N_EDGES;
}
__global__ void k_fill(const int* __restrict__ src, const int* __restrict__ dst) {
    int t = blockIdx.x * blockDim.x + threadIdx.x;
    if (t * 4 >= N_EDGES) return;
    int4 d = ((const int4*)dst)[t];
    int4 s = ((const int4*)src)[t];
    int p0 = g_off[d.x] + atomicAdd(&g_cur[d.x], 1);
    int p1 = g_off[d.y] + atomicAdd(&g_cur[d.y], 1);
    int p2 = g_off[d.z] + atomicAdd(&g_cur[d.z], 1);
    int p3 = g_off[d.w] + atomicAdd(&g_cur[d.w], 1);
    g_csr[p0] = s.x; g_csr[p1] = s.y; g_csr[p2] = s.z; g_csr[p3] = s.w;
}

// ---------------- GEMM1: fused token-gather, fp32 A staged in smem, K=256 ----------------
#define SROWW 20                               // fp16 W row stride (u32 words)
#define AROWW 36                               // fp32 A row stride (f32 words)
#define G1_A_B    (128 * AROWW * 4)            // 18432 B
#define G1_W_B    (128 * SROWW * 4)            // 10240 B per plane
#define G1_STAGE  (G1_A_B + 2 * G1_W_B)        // 38912 B
#define G1_SMEM   (2 * G1_STAGE + 512)         // 78336 B

__global__ void __launch_bounds__(256)
k_gemm1g(const float* __restrict__ embed, const int* __restrict__ tokens,
         const __half* __restrict__ Whi, const __half* __restrict__ Wlo,
         const float* __restrict__ bias, __half* __restrict__ Oh)
{
    extern __shared__ __align__(16) char smem_dyn[];
    const uint32_t sbase = (uint32_t)__cvta_generic_to_shared(smem_dyn);
    int* sTok = (int*)(smem_dyn + 2 * G1_STAGE);

    const int tid  = threadIdx.x;
    const int wid  = tid >> 5;
    const int lane = tid & 31;
    const int m_base = (wid >> 1) * 32;
    const int n_base = (wid & 1) * 64;
    const int n0   = blockIdx.x * 128;
    const int qr = lane >> 2;
    const int qj = lane & 3;
    constexpr int K = D_IN, NCH = K / 32;

    if (tid < 128) {
        int node = n0 + tid; if (node >= N_NODES) node = N_NODES - 1;
        sTok[tid] = tokens[node];
    }
    __syncthreads();

    auto issue = [&](int c, int buf) {
        #pragma unroll
        for (int it = 0; it < 8; it++) {       // 1024 A-fp32 uint4 + 1024 W uint4
            int i = it * 256 + tid;
            if (i < 1024) {
                int r = i >> 3, q = i & 7;     // q: 4-float group within 32 cols
                const char* src = (const char*)(embed + (size_t)sTok[r] * K + c * 32 + q * 4);
                uint32_t dstb = sbase + buf * G1_STAGE + r * (AROWW * 4) + q * 16;
                cp_async16(dstb, src);
            } else {
                int j = i - 1024;
                int plane = j >> 9;
                int r = (j >> 2) & 127;
                int q = j & 3;
                const __half* P = plane ? Wlo : Whi;
                const char* src = (const char*)P + ((size_t)r * K + c * 32 + q * 8) * 2;
                uint32_t dstb = sbase + buf * G1_STAGE + G1_A_B + plane * G1_W_B
                              + r * (SROWW * 4) + q * 16;
                cp_async16(dstb, src);
            }
        }
        cp_commit();
    };

    float acc[2][8][4];
    #pragma unroll
    for (int mt = 0; mt < 2; mt++)
        #pragma unroll
        for (int nt = 0; nt < 8; nt++)
            #pragma unroll
            for (int q = 0; q < 4; q++) acc[mt][nt][q] = 0.f;

    issue(0, 0);
    issue(1, 1);

    #pragma unroll
    for (int c = 0; c < NCH; c++) {
        if (c + 1 < NCH) cp_wait<1>(); else cp_wait<0>();
        __syncthreads();
        const char* stage = smem_dyn + (c & 1) * G1_STAGE;
        const float* sA  = (const float*)stage;
        const uint32_t* sWh = (const uint32_t*)(stage + G1_A_B);
        const uint32_t* sWl = (const uint32_t*)(stage + G1_A_B + G1_W_B);

        #pragma unroll
        for (int ks = 0; ks < 2; ks++) {
            const int kw = ks * 8 + qj;        // col-pair index 0..15
            uint32_t a[2][4];
            #pragma unroll
            for (int mt = 0; mt < 2; mt++) {
                int r0 = (m_base + mt * 16 + qr) * AROWW;
                int r1 = (m_base + mt * 16 + qr + 8) * AROWW;
                float2 v00 = *(const float2*)&sA[r0 + 2 * kw];
                float2 v10 = *(const float2*)&sA[r1 + 2 * kw];
                float2 v01 = *(const float2*)&sA[r0 + 2 * kw + 8];
                float2 v11 = *(const float2*)&sA[r1 + 2 * kw + 8];
                a[mt][0] = packh2(v00.x, v00.y);
                a[mt][1] = packh2(v10.x, v10.y);
                a[mt][2] = packh2(v01.x, v01.y);
                a[mt][3] = packh2(v11.x, v11.y);
            }
            #pragma unroll
            for (int nt = 0; nt < 8; nt++) {
                int nr = (n_base + nt * 8 + qr) * SROWW;
                uint32_t bh0 = sWh[nr + kw], bh1 = sWh[nr + kw + 4];
                uint32_t bl0 = sWl[nr + kw], bl1 = sWl[nr + kw + 4];
                #pragma unroll
                for (int mt = 0; mt < 2; mt++) {
                    mma16816h(acc[mt][nt], a[mt][0], a[mt][1], a[mt][2], a[mt][3], bh0, bh1);
                    mma16816h(acc[mt][nt], a[mt][0], a[mt][1], a[mt][2], a[mt][3], bl0, bl1);
                }
            }
        }
        __syncthreads();
        if (c + 2 < NCH) issue(c + 2, c & 1);
    }

    // epilogue: +bias, *dinv*256, fp16 out
    #pragma unroll
    for (int mt = 0; mt < 2; mt++) {
        int r0 = n0 + m_base + mt * 16 + qr;
        int r1 = r0 + 8;
        float d0 = (r0 < N_NODES) ? g_dinv[r0] * 256.f : 0.f;
        float d1 = (r1 < N_NODES) ? g_dinv[r1] * 256.f : 0.f;
        #pragma unroll
        for (int nt = 0; nt < 8; nt++) {
            int col = n_base + nt * 8 + qj * 2;
            float b0 = bias[col], b1 = bias[col + 1];
            if (r0 < N_NODES) {
                __half2 h = __floats2half2_rn((acc[mt][nt][0] + b0) * d0, (acc[mt][nt][1] + b1) * d0);
                ((uint32_t*)Oh)[(size_t)r0 * 64 + (col >> 1)] = *(uint32_t*)&h;
            }
            if (r1 < N_NODES) {
                __half2 h = __floats2half2_rn((acc[mt][nt][2] + b0) * d1, (acc[mt][nt][3] + b1) * d1);
                ((uint32_t*)Oh)[(size_t)r1 * 64 + (col >> 1)] = *(uint32_t*)&h;
            }
        }
    }
}

// ---------------- GEMM2/3: cp.async double-buffered, A fp16 from gmem (K=128) ----------------
#define STAGE_W   (3 * 128 * SROWW)
#define STAGE_B   (STAGE_W * 4)
#define SMEM_DYN  (2 * STAGE_B)            // 61440 B

template<int K, bool RELU_OUT, bool HALF_OUT, bool SCALE>
__global__ void __launch_bounds__(256)
k_gemm(const __half* __restrict__ A,
       const __half* __restrict__ Whi, const __half* __restrict__ Wlo,
       const float* __restrict__ bias, __half* __restrict__ Oh, float* __restrict__ Of)
{
    extern __shared__ __align__(16) char smem_dyn[];
    uint32_t* S = (uint32_t*)smem_dyn;
    const uint32_t sbase = (uint32_t)__cvta_generic_to_shared(smem_dyn);

    const int tid  = threadIdx.x;
    const int wid  = tid >> 5;
    const int lane = tid & 31;
    const int m_base = (wid >> 1) * 32;
    const int n_base = (wid & 1) * 64;
    const int n0   = blockIdx.x * 128;
    const int qr = lane >> 2;
    const int qj = lane & 3;
    constexpr int NCH = K / 32;

    auto issue = [&](int c, int buf) {
        #pragma unroll
        for (int it = 0; it < 6; it++) {
            int i     = it * 256 + tid;
            int plane = i >> 9;
            int r     = (i >> 2) & 127;
            int q     = i & 3;
            const __half* P = (plane == 0) ? A : (plane == 1) ? Whi : Wlo;
            int rg;
            if (plane == 0) { int node = n0 + r; if (node >= N_NODES) node = N_NODES - 1; rg = node; }
            else            rg = r;
            const char* src = (const char*)P + ((size_t)rg * K + c * 32 + q * 8) * 2;
            uint32_t dstb = sbase + buf * STAGE_B + plane * (128 * SROWW * 4)
                          + r * (SROWW * 4) + q * 16;
            cp_async16(dstb, src);
        }
        cp_commit();
    };

    float acc[2][8][4];
    #pragma unroll
    for (int mt = 0; mt < 2; mt++)
        #pragma unroll
        for (int nt = 0; nt < 8; nt++)
            #pragma unroll
            for (int q = 0; q < 4; q++) acc[mt][nt][q] = 0.f;

    issue(0, 0);
    issue(1, 1);

    #pragma unroll
    for (int c = 0; c < NCH; c++) {
        if (c + 1 < NCH) cp_wait<1>(); else cp_wait<0>();
        __syncthreads();
        const int bw = (c & 1) * STAGE_W;
        uint32_t* sA  = S + bw;
        uint32_t* sWh = S + bw + 128 * SROWW;
        uint32_t* sWl = S + bw + 2 * 128 * SROWW;
        #pragma unroll
        for (int ks = 0; ks < 2; ks++) {
            const int kw = ks * 8 + qj;
            uint32_t a[2][4];
            #pragma unroll
            for (int mt = 0; mt < 2; mt++) {
                int r0 = (m_base + mt * 16 + qr) * SROWW;
                int r1 = (m_base + mt * 16 + qr + 8) * SROWW;
                a[mt][0] = sA[r0 + kw];     a[mt][1] = sA[r1 + kw];
                a[mt][2] = sA[r0 + kw + 4]; a[mt][3] = sA[r1 + kw + 4];
            }
            #pragma unroll
            for (int nt = 0; nt < 8; nt++) {
                int nr = (n_base + nt * 8 + qr) * SROWW;
                uint32_t bh0 = sWh[nr + kw], bh1 = sWh[nr + kw + 4];
                uint32_t bl0 = sWl[nr + kw], bl1 = sWl[nr + kw + 4];
                #pragma unroll
                for (int mt = 0; mt < 2; mt++) {
                    mma16816h(acc[mt][nt], a[mt][0], a[mt][1], a[mt][2], a[mt][3], bh0, bh1);
                    mma16816h(acc[mt][nt], a[mt][0], a[mt][1], a[mt][2], a[mt][3], bl0, bl1);
                }
            }
        }
        __syncthreads();
        if (c + 2 < NCH) issue(c + 2, c & 1);
    }

    #pragma unroll
    for (int mt = 0; mt < 2; mt++) {
        int r0 = n0 + m_base + mt * 16 + qr;
        int r1 = r0 + 8;
        float d0 = 1.f, d1 = 1.f;
        if (SCALE) {
            d0 = (r0 < N_NODES) ? g_dinv[r0] * 256.f : 0.f;
            d1 = (r1 < N_NODES) ? g_dinv[r1] * 256.f : 0.f;
        }
        #pragma unroll
        for (int nt = 0; nt < 8; nt++) {
            int col = n_base + nt * 8 + qj * 2;
            float b0 = bias[col], b1 = bias[col + 1];
            float vx0 = acc[mt][nt][0] + b0, vy0 = acc[mt][nt][1] + b1;
            float vx1 = acc[mt][nt][2] + b0, vy1 = acc[mt][nt][3] + b1;
            if (RELU_OUT) {
                vx0 = fmaxf(vx0, 0.f); vy0 = fmaxf(vy0, 0.f);
                vx1 = fmaxf(vx1, 0.f); vy1 = fmaxf(vy1, 0.f);
            }
            if (SCALE) { vx0 *= d0; vy0 *= d0; vx1 *= d1; vy1 *= d1; }
            if (HALF_OUT) {
                if (r0 < N_NODES) {
                    __half2 h = __floats2half2_rn(vx0, vy0);
                    ((uint32_t*)Oh)[(size_t)r0 * 64 + (col >> 1)] = *(uint32_t*)&h;
                }
                if (r1 < N_NODES) {
                    __half2 h = __floats2half2_rn(vx1, vy1);
                    ((uint32_t*)Oh)[(size_t)r1 * 64 + (col >> 1)] = *(uint32_t*)&h;
                }
            } else {
                if (r0 < N_NODES)
                    *(float2*)(Of + (size_t)r0 * D_OUT + col) = make_float2(vx0, vy0);
                if (r1 < N_NODES)
                    *(float2*)(Of + (size_t)r1 * D_OUT + col) = make_float2(vx1, vy1);
            }
        }
    }
}

// ---------------- aggregation: fp16 prescaled(*256) in -> fp16 out, unroll 8 ----------------
__global__ void k_agg(const __half* __restrict__ x, __half* __restrict__ z)
{
    int gw   = (blockIdx.x * blockDim.x + threadIdx.x) >> 5;
    int lane = threadIdx.x & 31;
    if (gw >= N_NODES) return;

    const uint2* x4 = (const uint2*)x;
    float a[4] = {0.f, 0.f, 0.f, 0.f};
    hacc(a, x4[(size_t)gw * 32 + lane]);  // self

    int b = g_off[gw], e = g_off[gw + 1];
    int i = b;
    for (; i + 8 <= e; i += 8) {
        int s0 = g_csr[i],   s1 = g_csr[i+1], s2 = g_csr[i+2], s3 = g_csr[i+3];
        int s4 = g_csr[i+4], s5 = g_csr[i+5], s6 = g_csr[i+6], s7 = g_csr[i+7];
        uint2 v0 = x4[(size_t)s0 * 32 + lane];
        uint2 v1 = x4[(size_t)s1 * 32 + lane];
        uint2 v2 = x4[(size_t)s2 * 32 + lane];
        uint2 v3 = x4[(size_t)s3 * 32 + lane];
        uint2 v4 = x4[(size_t)s4 * 32 + lane];
        uint2 v5 = x4[(size_t)s5 * 32 + lane];
        uint2 v6 = x4[(size_t)s6 * 32 + lane];
        uint2 v7 = x4[(size_t)s7 * 32 + lane];
        hacc(a, v0); hacc(a, v1); hacc(a, v2); hacc(a, v3);
        hacc(a, v4); hacc(a, v5); hacc(a, v6); hacc(a, v7);
    }
    for (; i + 4 <= e; i += 4) {
        int s0 = g_csr[i], s1 = g_csr[i+1], s2 = g_csr[i+2], s3 = g_csr[i+3];
        uint2 v0 = x4[(size_t)s0 * 32 + lane];
        uint2 v1 = x4[(size_t)s1 * 32 + lane];
        uint2 v2 = x4[(size_t)s2 * 32 + lane];
        uint2 v3 = x4[(size_t)s3 * 32 + lane];
        hacc(a, v0); hacc(a, v1); hacc(a, v2); hacc(a, v3);
    }
    for (; i < e; i++) {
        int s = g_csr[i];
        hacc(a, x4[(size_t)s * 32 + lane]);
    }

    float di = g_dinv[gw] * (1.f / 256.f);
    __half2 o0 = __floats2half2_rn(a[0] * di, a[1] * di);
    __half2 o1 = __floats2half2_rn(a[2] * di, a[3] * di);
    uint2 o = { *(uint32_t*)&o0, *(uint32_t*)&o1 };
    ((uint2*)z)[(size_t)gw * 32 + lane] = o;
}

// ---------------- launch ----------------
extern "C" void kernel_launch(void* const* d_in, const int* in_sizes, int n_in,
                              void* d_out, int out_size)
{
    const int*   tokens = (const int*)  d_in[0];
    const int*   eidx   = (const int*)  d_in[1];
    const float* embed  = (const float*)d_in[2];
    const float* Wn     = (const float*)d_in[3];
    const float* Wb     = (const float*)d_in[4];
    const float* w1     = (const float*)d_in[5];
    const float* b1     = (const float*)d_in[6];
    const float* w2     = (const float*)d_in[7];
    const float* b2     = (const float*)d_in[8];
    float* out = (float*)d_out;

    const int* src = eidx;
    const int* dst = eidx + N_EDGES;

    __half *Z, *xh, *hh, *Wnh, *Wnl, *w1h, *w1l, *w2h, *w2l;
    cudaGetSymbolAddress((void**)&Z,   g_Z);
    cudaGetSymbolAddress((void**)&xh,  g_xh);  cudaGetSymbolAddress((void**)&hh,  g_hh);
    cudaGetSymbolAddress((void**)&Wnh, g_Wnh); cudaGetSymbolAddress((void**)&Wnl, g_Wnl);
    cudaGetSymbolAddress((void**)&w1h, g_w1h); cudaGetSymbolAddress((void**)&w1l, g_w1l);
    cudaGetSymbolAddress((void**)&w2h, g_w2h); cudaGetSymbolAddress((void**)&w2l, g_w2l);

    cudaFuncSetAttribute(k_gemm1g, cudaFuncAttributeMaxDynamicSharedMemorySize, G1_SMEM);
    cudaFuncSetAttribute(k_gemm<D_OUT, true,  true,  true >, cudaFuncAttributeMaxDynamicSharedMemorySize, SMEM_DYN);
    cudaFuncSetAttribute(k_gemm<D_OUT, false, false, false>, cudaFuncAttributeMaxDynamicSharedMemorySize, SMEM_DYN);

    static cudaStream_t sB = nullptr;
    static cudaEvent_t evFork = nullptr, evDinv = nullptr, evCsr = nullptr;
    if (!sB) {
        cudaStreamCreateWithFlags(&sB, cudaStreamNonBlocking);
        cudaEventCreateWithFlags(&evFork, cudaEventDisableTiming);
        cudaEventCreateWithFlags(&evDinv, cudaEventDisableTiming);
        cudaEventCreateWithFlags(&evCsr,  cudaEventDisableTiming);
    }

    const int NB_N  = (N_NODES + 255) / 256;
    const int NB_E4 = (N_EDGES / 4 + 255) / 256;
    const int NB_G  = (N_NODES + 127) / 128;
    const int NB_C  = (N_NODES * 32 + 255) / 256;

    // fork
    cudaEventRecord(evFork, 0);
    cudaStreamWaitEvent(sB, evFork, 0);

    // stream B: weight split (hidden), then graph structure
    k_splitw<<<64,   256, 0, sB>>>(Wn, w1, w2);
    k_zero  <<<NB_N,  256, 0, sB>>>();
    k_count <<<NB_E4, 256, 0, sB>>>(dst);
    k_scan1 <<<NB_N,  256, 0, sB>>>();
    cudaEventRecord(evDinv, sB);               // dinv + W planes ready
    k_scan23<<<NB_N,  256, 0, sB>>>();
    k_fill  <<<NB_E4, 256, 0, sB>>>(src, dst);
    cudaEventRecord(evCsr, sB);                // CSR ready

    // stream 0: GEMM1 with fused embed gather (needs dinv + W planes)
    cudaStreamWaitEvent(0, evDinv, 0);
    k_gemm1g<<<NB_G, 256, G1_SMEM>>>(embed, tokens, Wnh, Wnl, Wb, xh);

    // agg1 (needs CSR)
    cudaStreamWaitEvent(0, evCsr, 0);
    k_agg<<<NB_C, 256>>>(xh, Z);
    // GEMM2: h' = relu(Z @ w1^T + b1) * dinv*256
    k_gemm<D_OUT, true, true, true><<<NB_G, 256, SMEM_DYN>>>(Z, w1h, w1l, b1, hh, nullptr);
    // agg2
    k_agg<<<NB_C, 256>>>(hh, Z);
    // GEMM3: out = Z @ w2^T + b2
    k_gemm<D_OUT, false, false, false><<<NB_G, 256, SMEM_DYN>>>(Z, w2h, w2l, b2, nullptr, out);
}

// round 16
// speedup vs baseline: 1.6373x; 1.0185x over previous
#include <cuda_runtime.h>
#include <cuda_bf16.h>
#include <cuda_fp16.h>
#include <cstdint>

#define N_NODES 50000
#define N_EDGES 600000
#define D_IN    256
#define D_OUT   128

// ---------------- scratch (static device globals; no allocation) ----------------
__device__ __half g_Z [N_NODES * D_OUT];   // agg output, fp16
__device__ __half g_xh[N_NODES * D_OUT];   // gemm1 out (prescaled*256, fp16)
__device__ __half g_hh[N_NODES * D_OUT];   // gemm2 out (relu, prescaled*256, fp16)
__device__ __half g_Wnh[128 * D_IN],  g_Wnl[128 * D_IN];
__device__ __half g_w1h[128 * D_OUT], g_w1l[128 * D_OUT];
__device__ __half g_w2h[128 * D_OUT], g_w2l[128 * D_OUT];

__device__ float g_dinv[N_NODES];
__device__ int   g_deg [N_NODES];          // zero-init at load; re-zeroed by k_scan23 each call
__device__ int   g_cur [N_NODES];
__device__ int   g_off [N_NODES + 1];
__device__ int   g_bsum [256];
__device__ int   g_csr [N_EDGES];

// ---------------- helpers ----------------
__device__ __forceinline__ void wsplit2(float x, float y, uint32_t& hi, uint32_t& lo) {
    __half2 h = __floats2half2_rn(x, y);
    float2 hf = __half22float2(h);
    __half2 l = __floats2half2_rn(x - hf.x, y - hf.y);
    hi = *(uint32_t*)&h; lo = *(uint32_t*)&l;
}
__device__ __forceinline__ void cp_async16(uint32_t saddr, const void* gaddr) {
    asm volatile("cp.async.cg.shared.global [%0], [%1], 16;" :: "r"(saddr), "l"(gaddr));
}
__device__ __forceinline__ void cp_commit() {
    asm volatile("cp.async.commit_group;" ::: "memory");
}
template<int N> __device__ __forceinline__ void cp_wait() {
    asm volatile("cp.async.wait_group %0;" :: "n"(N) : "memory");
}
__device__ __forceinline__ void mma16816h(float* d, uint32_t a0, uint32_t a1,
                                          uint32_t a2, uint32_t a3,
                                          uint32_t b0, uint32_t b1) {
    asm volatile(
        "mma.sync.aligned.m16n8k16.row.col.f32.f16.f16.f32 "
        "{%0,%1,%2,%3}, {%4,%5,%6,%7}, {%8,%9}, {%0,%1,%2,%3};"
        : "+f"(d[0]), "+f"(d[1]), "+f"(d[2]), "+f"(d[3])
        : "r"(a0), "r"(a1), "r"(a2), "r"(a3), "r"(b0), "r"(b1));
}
__device__ __forceinline__ void hacc(float* a, uint2 v) {
    float2 p0 = __half22float2(*(__half2*)&v.x);
    float2 p1 = __half22float2(*(__half2*)&v.y);
    a[0] += p0.x; a[1] += p0.y; a[2] += p1.x; a[3] += p1.y;
}
__device__ __forceinline__ uint32_t packh2(float x, float y) {
    __half2 h = __floats2half2_rn(x, y);
    return *(uint32_t*)&h;
}

// ---------------- weight split (main stream; overlaps stream B's count) ----------------
__global__ void k_splitw(const float* __restrict__ Wn, const float* __restrict__ w1,
                         const float* __restrict__ w2) {
    int i = blockIdx.x * 256 + threadIdx.x;
    const float* s; __half *ph, *pl; int off;
    if (i < 8192)       { s = Wn; ph = g_Wnh; pl = g_Wnl; off = i; }
    else if (i < 12288) { s = w1; ph = g_w1h; pl = g_w1l; off = i - 8192; }
    else                { s = w2; ph = g_w2h; pl = g_w2l; off = i - 12288; }
    float4 v = ((const float4*)s)[off];
    uint2 hi, lo;
    wsplit2(v.x, v.y, hi.x, lo.x);
    wsplit2(v.z, v.w, hi.y, lo.y);
    ((uint2*)ph)[off] = hi; ((uint2*)pl)[off] = lo;
}

// ---------------- graph-structure kernels ----------------
// g_deg arrives zeroed (module init on first call; k_scan23 re-zeroes thereafter)
__global__ void k_count(const int* __restrict__ dst) {
    int t = blockIdx.x * blockDim.x + threadIdx.x;
    if (t * 4 >= N_EDGES) return;
    int4 d = ((const int4*)dst)[t];
    atomicAdd(&g_deg[d.x], 1); atomicAdd(&g_deg[d.y], 1);
    atomicAdd(&g_deg[d.z], 1); atomicAdd(&g_deg[d.w], 1);
}
__global__ void k_scan1() {
    __shared__ int s[256];
    int i = blockIdx.x * 256 + threadIdx.x;
    int v = (i < N_NODES) ? g_deg[i] : 0;
    if (i < N_NODES) g_dinv[i] = rsqrtf((float)(v + 1));
    s[threadIdx.x] = v; __syncthreads();
    for (int d = 128; d > 0; d >>= 1) {
        if (threadIdx.x < d) s[threadIdx.x] += s[threadIdx.x + d];
        __syncthreads();
    }
    if (threadIdx.x == 0) g_bsum[blockIdx.x] = s[0];
}
// fused scan; zeroes g_cur AND g_deg (deg ready-zeroed for the next call/replay)
__global__ void k_scan23() {
    __shared__ int bs[256];
    __shared__ int s[256];
    int t = threadIdx.x;
    int nblk = gridDim.x;
    int bv = (t < nblk) ? g_bsum[t] : 0;
    bs[t] = bv; __syncthreads();
    for (int d = 1; d < 256; d <<= 1) {
        int u = (t >= d) ? bs[t - d] : 0;
        __syncthreads(); bs[t] += u; __syncthreads();
    }
    int base = blockIdx.x ? bs[blockIdx.x - 1] : 0;
    int i = blockIdx.x * 256 + t;
    int v = (i < N_NODES) ? g_deg[i] : 0;
    s[t] = v; __syncthreads();
    for (int d = 1; d < 256; d <<= 1) {
        int u = (t >= d) ? s[t - d] : 0;
        __syncthreads(); s[t] += u; __syncthreads();
    }
    if (i < N_NODES) { g_off[i] = base + s[t] - v; g_cur[i] = 0; g_deg[i] = 0; }
    if (i == 0) g_off[N_NODES] = N_EDGES;
}
__global__ void k_fill(const int* __restrict__ src, const int* __restrict__ dst) {
    int t = blockIdx.x * blockDim.x + threadIdx.x;
    if (t * 4 >= N_EDGES) return;
    int4 d = ((const int4*)dst)[t];
    int4 s = ((const int4*)src)[t];
    int p0 = g_off[d.x] + atomicAdd(&g_cur[d.x], 1);
    int p1 = g_off[d.y] + atomicAdd(&g_cur[d.y], 1);
    int p2 = g_off[d.z] + atomicAdd(&g_cur[d.z], 1);
    int p3 = g_off[d.w] + atomicAdd(&g_cur[d.w], 1);
    g_csr[p0] = s.x; g_csr[p1] = s.y; g_csr[p2] = s.z; g_csr[p3] = s.w;
}

// ---------------- GEMM1: fused token-gather, fp32 A staged in smem, K=256 ----------------
#define SROWW 20                               // fp16 W row stride (u32 words)
#define AROWW 36                               // fp32 A row stride (f32 words)
#define G1_A_B    (128 * AROWW * 4)            // 18432 B
#define G1_W_B    (128 * SROWW * 4)            // 10240 B per plane
#define G1_STAGE  (G1_A_B + 2 * G1_W_B)        // 38912 B
#define G1_SMEM   (2 * G1_STAGE)               // 77824 B

__global__ void __launch_bounds__(256)
k_gemm1g(const float* __restrict__ embed, const int* __restrict__ tokens,
         const __half* __restrict__ Whi, const __half* __restrict__ Wlo,
         const float* __restrict__ bias, __half* __restrict__ Oh)
{
    extern __shared__ __align__(16) char smem_dyn[];
    const uint32_t sbase = (uint32_t)__cvta_generic_to_shared(smem_dyn);

    const int tid  = threadIdx.x;
    const int wid  = tid >> 5;
    const int lane = tid & 31;
    const int m_base = (wid >> 1) * 32;
    const int n_base = (wid & 1) * 64;
    const int n0   = blockIdx.x * 128;
    const int qr = lane >> 2;
    const int qj = lane & 3;
    constexpr int K = D_IN, NCH = K / 32;

    // each thread's 4 A-rows are fixed: r = (it*256+tid)>>3 — keep tokens in regs
    int rtok[4];
    #pragma unroll
    for (int it = 0; it < 4; it++) {
        int r = (it * 256 + tid) >> 3;
        int node = n0 + r; if (node >= N_NODES) node = N_NODES - 1;
        rtok[it] = __ldg(&tokens[node]);
    }

    auto issue = [&](int c, int buf) {
        #pragma unroll
        for (int it = 0; it < 8; it++) {       // 1024 A-fp32 uint4 + 1024 W uint4
            int i = it * 256 + tid;
            if (it < 4) {
                int r = i >> 3, q = i & 7;
                const char* src = (const char*)(embed + (size_t)rtok[it] * K + c * 32 + q * 4);
                uint32_t dstb = sbase + buf * G1_STAGE + r * (AROWW * 4) + q * 16;
                cp_async16(dstb, src);
            } else {
                int j = i - 1024;
                int plane = j >> 9;
                int r = (j >> 2) & 127;
                int q = j & 3;
                const __half* P = plane ? Wlo : Whi;
                const char* src = (const char*)P + ((size_t)r * K + c * 32 + q * 8) * 2;
                uint32_t dstb = sbase + buf * G1_STAGE + G1_A_B + plane * G1_W_B
                              + r * (SROWW * 4) + q * 16;
                cp_async16(dstb, src);
            }
        }
        cp_commit();
    };

    float acc[2][8][4];
    #pragma unroll
    for (int mt = 0; mt < 2; mt++)
        #pragma unroll
        for (int nt = 0; nt < 8; nt++)
            #pragma unroll
            for (int q = 0; q < 4; q++) acc[mt][nt][q] = 0.f;

    issue(0, 0);
    issue(1, 1);

    #pragma unroll
    for (int c = 0; c < NCH; c++) {
        if (c + 1 < NCH) cp_wait<1>(); else cp_wait<0>();
        __syncthreads();
        const char* stage = smem_dyn + (c & 1) * G1_STAGE;
        const float* sA  = (const float*)stage;
        const uint32_t* sWh = (const uint32_t*)(stage + G1_A_B);
        const uint32_t* sWl = (const uint32_t*)(stage + G1_A_B + G1_W_B);

        #pragma unroll
        for (int ks = 0; ks < 2; ks++) {
            const int kw = ks * 8 + qj;        // col-pair index 0..15
            uint32_t a[2][4];
            #pragma unroll
            for (int mt = 0; mt < 2; mt++) {
                int r0 = (m_base + mt * 16 + qr) * AROWW;
                int r1 = (m_base + mt * 16 + qr + 8) * AROWW;
                float2 v00 = *(const float2*)&sA[r0 + 2 * kw];
                float2 v10 = *(const float2*)&sA[r1 + 2 * kw];
                float2 v01 = *(const float2*)&sA[r0 + 2 * kw + 8];
                float2 v11 = *(const float2*)&sA[r1 + 2 * kw + 8];
                a[mt][0] = packh2(v00.x, v00.y);
                a[mt][1] = packh2(v10.x, v10.y);
                a[mt][2] = packh2(v01.x, v01.y);
                a[mt][3] = packh2(v11.x, v11.y);
            }
            #pragma unroll
            for (int nt = 0; nt < 8; nt++) {
                int nr = (n_base + nt * 8 + qr) * SROWW;
                uint32_t bh0 = sWh[nr + kw], bh1 = sWh[nr + kw + 4];
                uint32_t bl0 = sWl[nr + kw], bl1 = sWl[nr + kw + 4];
                #pragma unroll
                for (int mt = 0; mt < 2; mt++) {
                    mma16816h(acc[mt][nt], a[mt][0], a[mt][1], a[mt][2], a[mt][3], bh0, bh1);
                    mma16816h(acc[mt][nt], a[mt][0], a[mt][1], a[mt][2], a[mt][3], bl0, bl1);
                }
            }
        }
        __syncthreads();
        if (c + 2 < NCH) issue(c + 2, c & 1);
    }

    // epilogue: +bias, *dinv*256, fp16 out
    #pragma unroll
    for (int mt = 0; mt < 2; mt++) {
        int r0 = n0 + m_base + mt * 16 + qr;
        int r1 = r0 + 8;
        float d0 = (r0 < N_NODES) ? g_dinv[r0] * 256.f : 0.f;
        float d1 = (r1 < N_NODES) ? g_dinv[r1] * 256.f : 0.f;
        #pragma unroll
        for (int nt = 0; nt < 8; nt++) {
            int col = n_base + nt * 8 + qj * 2;
            float b0 = bias[col], b1 = bias[col + 1];
            if (r0 < N_NODES) {
                __half2 h = __floats2half2_rn((acc[mt][nt][0] + b0) * d0, (acc[mt][nt][1] + b1) * d0);
                ((uint32_t*)Oh)[(size_t)r0 * 64 + (col >> 1)] = *(uint32_t*)&h;
            }
            if (r1 < N_NODES) {
                __half2 h = __floats2half2_rn((acc[mt][nt][2] + b0) * d1, (acc[mt][nt][3] + b1) * d1);
                ((uint32_t*)Oh)[(size_t)r1 * 64 + (col >> 1)] = *(uint32_t*)&h;
            }
        }
    }
}

// ---------------- GEMM2/3: cp.async double-buffered, A fp16 from gmem (K=128) ----------------
#define STAGE_W   (3 * 128 * SROWW)
#define STAGE_B   (STAGE_W * 4)
#define SMEM_DYN  (2 * STAGE_B)            // 61440 B

template<int K, bool RELU_OUT, bool HALF_OUT, bool SCALE>
__global__ void __launch_bounds__(256)
k_gemm(const __half* __restrict__ A,
       const __half* __restrict__ Whi, const __half* __restrict__ Wlo,
       const float* __restrict__ bias, __half* __restrict__ Oh, float* __restrict__ Of)
{
    extern __shared__ __align__(16) char smem_dyn[];
    uint32_t* S = (uint32_t*)smem_dyn;
    const uint32_t sbase = (uint32_t)__cvta_generic_to_shared(smem_dyn);

    const int tid  = threadIdx.x;
    const int wid  = tid >> 5;
    const int lane = tid & 31;
    const int m_base = (wid >> 1) * 32;
    const int n_base = (wid & 1) * 64;
    const int n0   = blockIdx.x * 128;
    const int qr = lane >> 2;
    const int qj = lane & 3;
    constexpr int NCH = K / 32;

    auto issue = [&](int c, int buf) {
        #pragma unroll
        for (int it = 0; it < 6; it++) {
            int i     = it * 256 + tid;
            int plane = i >> 9;
            int r     = (i >> 2) & 127;
            int q     = i & 3;
            const __half* P = (plane == 0) ? A : (plane == 1) ? Whi : Wlo;
            int rg;
            if (plane == 0) { int node = n0 + r; if (node >= N_NODES) node = N_NODES - 1; rg = node; }
            else            rg = r;
            const char* src = (const char*)P + ((size_t)rg * K + c * 32 + q * 8) * 2;
            uint32_t dstb = sbase + buf * STAGE_B + plane * (128 * SROWW * 4)
                          + r * (SROWW * 4) + q * 16;
            cp_async16(dstb, src);
        }
        cp_commit();
    };

    float acc[2][8][4];
    #pragma unroll
    for (int mt = 0; mt < 2; mt++)
        #pragma unroll
        for (int nt = 0; nt < 8; nt++)
            #pragma unroll
            for (int q = 0; q < 4; q++) acc[mt][nt][q] = 0.f;

    issue(0, 0);
    issue(1, 1);

    #pragma unroll
    for (int c = 0; c < NCH; c++) {
        if (c + 1 < NCH) cp_wait<1>(); else cp_wait<0>();
        __syncthreads();
        const int bw = (c & 1) * STAGE_W;
        uint32_t* sA  = S + bw;
        uint32_t* sWh = S + bw + 128 * SROWW;
        uint32_t* sWl = S + bw + 2 * 128 * SROWW;
        #pragma unroll
        for (int ks = 0; ks < 2; ks++) {
            const int kw = ks * 8 + qj;
            uint32_t a[2][4];
            #pragma unroll
            for (int mt = 0; mt < 2; mt++) {
                int r0 = (m_base + mt * 16 + qr) * SROWW;
                int r1 = (m_base + mt * 16 + qr + 8) * SROWW;
                a[mt][0] = sA[r0 + kw];     a[mt][1] = sA[r1 + kw];
                a[mt][2] = sA[r0 + kw + 4]; a[mt][3] = sA[r1 + kw + 4];
            }
            #pragma unroll
            for (int nt = 0; nt < 8; nt++) {
                int nr = (n_base + nt * 8 + qr) * SROWW;
                uint32_t bh0 = sWh[nr + kw], bh1 = sWh[nr + kw + 4];
                uint32_t bl0 = sWl[nr + kw], bl1 = sWl[nr + kw + 4];
                #pragma unroll
                for (int mt = 0; mt < 2; mt++) {
                    mma16816h(acc[mt][nt], a[mt][0], a[mt][1], a[mt][2], a[mt][3], bh0, bh1);
                    mma16816h(acc[mt][nt], a[mt][0], a[mt][1], a[mt][2], a[mt][3], bl0, bl1);
                }
            }
        }
        __syncthreads();
        if (c + 2 < NCH) issue(c + 2, c & 1);
    }

    #pragma unroll
    for (int mt = 0; mt < 2; mt++) {
        int r0 = n0 + m_base + mt * 16 + qr;
        int r1 = r0 + 8;
        float d0 = 1.f, d1 = 1.f;
        if (SCALE) {
            d0 = (r0 < N_NODES) ? g_dinv[r0] * 256.f : 0.f;
            d1 = (r1 < N_NODES) ? g_dinv[r1] * 256.f : 0.f;
        }
        #pragma unroll
        for (int nt = 0; nt < 8; nt++) {
            int col = n_base + nt * 8 + qj * 2;
            float b0 = bias[col], b1 = bias[col + 1];
            float vx0 = acc[mt][nt][0] + b0, vy0 = acc[mt][nt][1] + b1;
            float vx1 = acc[mt][nt][2] + b0, vy1 = acc[mt][nt][3] + b1;
            if (RELU_OUT) {
                vx0 = fmaxf(vx0, 0.f); vy0 = fmaxf(vy0, 0.f);
                vx1 = fmaxf(vx1, 0.f); vy1 = fmaxf(vy1, 0.f);
            }
            if (SCALE) { vx0 *= d0; vy0 *= d0; vx1 *= d1; vy1 *= d1; }
            if (HALF_OUT) {
                if (r0 < N_NODES) {
                    __half2 h = __floats2half2_rn(vx0, vy0);
                    ((uint32_t*)Oh)[(size_t)r0 * 64 + (col >> 1)] = *(uint32_t*)&h;
                }
                if (r1 < N_NODES) {
                    __half2 h = __floats2half2_rn(vx1, vy1);
                    ((uint32_t*)Oh)[(size_t)r1 * 64 + (col >> 1)] = *(uint32_t*)&h;
                }
            } else {
                if (r0 < N_NODES)
                    *(float2*)(Of + (size_t)r0 * D_OUT + col) = make_float2(vx0, vy0);
                if (r1 < N_NODES)
                    *(float2*)(Of + (size_t)r1 * D_OUT + col) = make_float2(vx1, vy1);
            }
        }
    }
}

// ---------------- aggregation: fp16 prescaled(*256) in -> fp16 out, unroll 8 ----------------
__global__ void k_agg(const __half* __restrict__ x, __half* __restrict__ z)
{
    int gw   = (blockIdx.x * blockDim.x + threadIdx.x) >> 5;
    int lane = threadIdx.x & 31;
    if (gw >= N_NODES) return;

    const uint2* x4 = (const uint2*)x;
    float a[4] = {0.f, 0.f, 0.f, 0.f};
    hacc(a, x4[(size_t)gw * 32 + lane]);  // self

    int b = g_off[gw], e = g_off[gw + 1];
    int i = b;
    for (; i + 8 <= e; i += 8) {
        int s0 = g_csr[i],   s1 = g_csr[i+1], s2 = g_csr[i+2], s3 = g_csr[i+3];
        int s4 = g_csr[i+4], s5 = g_csr[i+5], s6 = g_csr[i+6], s7 = g_csr[i+7];
        uint2 v0 = x4[(size_t)s0 * 32 + lane];
        uint2 v1 = x4[(size_t)s1 * 32 + lane];
        uint2 v2 = x4[(size_t)s2 * 32 + lane];
        uint2 v3 = x4[(size_t)s3 * 32 + lane];
        uint2 v4 = x4[(size_t)s4 * 32 + lane];
        uint2 v5 = x4[(size_t)s5 * 32 + lane];
        uint2 v6 = x4[(size_t)s6 * 32 + lane];
        uint2 v7 = x4[(size_t)s7 * 32 + lane];
        hacc(a, v0); hacc(a, v1); hacc(a, v2); hacc(a, v3);
        hacc(a, v4); hacc(a, v5); hacc(a, v6); hacc(a, v7);
    }
    for (; i + 4 <= e; i += 4) {
        int s0 = g_csr[i], s1 = g_csr[i+1], s2 = g_csr[i+2], s3 = g_csr[i+3];
        uint2 v0 = x4[(size_t)s0 * 32 + lane];
        uint2 v1 = x4[(size_t)s1 * 32 + lane];
        uint2 v2 = x4[(size_t)s2 * 32 + lane];
        uint2 v3 = x4[(size_t)s3 * 32 + lane];
        hacc(a, v0); hacc(a, v1); hacc(a, v2); hacc(a, v3);
    }
    for (; i < e; i++) {
        int s = g_csr[i];
        hacc(a, x4[(size_t)s * 32 + lane]);
    }

    float di = g_dinv[gw] * (1.f / 256.f);
    __half2 o0 = __floats2half2_rn(a[0] * di, a[1] * di);
    __half2 o1 = __floats2half2_rn(a[2] * di, a[3] * di);
    uint2 o = { *(uint32_t*)&o0, *(uint32_t*)&o1 };
    ((uint2*)z)[(size_t)gw * 32 + lane] = o;
}

// ---------------- launch ----------------
extern "C" void kernel_launch(void* const* d_in, const int* in_sizes, int n_in,
                              void* d_out, int out_size)
{
    const int*   tokens = (const int*)  d_in[0];
    const int*   eidx   = (const int*)  d_in[1];
    const float* embed  = (const float*)d_in[2];
    const float* Wn     = (const float*)d_in[3];
    const float* Wb     = (const float*)d_in[4];
    const float* w1     = (const float*)d_in[5];
    const float* b1     = (const float*)d_in[6];
    const float* w2     = (const float*)d_in[7];
    const float* b2     = (const float*)d_in[8];
    float* out = (float*)d_out;

    const int* src = eidx;
    const int* dst = eidx + N_EDGES;

    __half *Z, *xh, *hh, *Wnh, *Wnl, *w1h, *w1l, *w2h, *w2l;
    cudaGetSymbolAddress((void**)&Z,   g_Z);
    cudaGetSymbolAddress((void**)&xh,  g_xh);  cudaGetSymbolAddress((void**)&hh,  g_hh);
    cudaGetSymbolAddress((void**)&Wnh, g_Wnh); cudaGetSymbolAddress((void**)&Wnl, g_Wnl);
    cudaGetSymbolAddress((void**)&w1h, g_w1h); cudaGetSymbolAddress((void**)&w1l, g_w1l);
    cudaGetSymbolAddress((void**)&w2h, g_w2h); cudaGetSymbolAddress((void**)&w2l, g_w2l);

    cudaFuncSetAttribute(k_gemm1g, cudaFuncAttributeMaxDynamicSharedMemorySize, G1_SMEM);
    cudaFuncSetAttribute(k_gemm<D_OUT, true,  true,  true >, cudaFuncAttributeMaxDynamicSharedMemorySize, SMEM_DYN);
    cudaFuncSetAttribute(k_gemm<D_OUT, false, false, false>, cudaFuncAttributeMaxDynamicSharedMemorySize, SMEM_DYN);

    static cudaStream_t sB = nullptr;
    static cudaEvent_t evFork = nullptr, evDinv = nullptr, evCsr = nullptr;
    if (!sB) {
        cudaStreamCreateWithFlags(&sB, cudaStreamNonBlocking);
        cudaEventCreateWithFlags(&evFork, cudaEventDisableTiming);
        cudaEventCreateWithFlags(&evDinv, cudaEventDisableTiming);
        cudaEventCreateWithFlags(&evCsr,  cudaEventDisableTiming);
    }

    const int NB_N  = (N_NODES + 255) / 256;
    const int NB_E4 = (N_EDGES / 4 + 255) / 256;
    const int NB_G  = (N_NODES + 127) / 128;
    const int NB_C  = (N_NODES * 32 + 255) / 256;

    // fork
    cudaEventRecord(evFork, 0);
    cudaStreamWaitEvent(sB, evFork, 0);

    // stream B: graph structure (deg pre-zeroed by previous call's scan23 / module init)
    k_count <<<NB_E4, 256, 0, sB>>>(dst);
    k_scan1 <<<NB_N,  256, 0, sB>>>();
    cudaEventRecord(evDinv, sB);               // dinv ready
    k_scan23<<<NB_N,  256, 0, sB>>>();
    k_fill  <<<NB_E4, 256, 0, sB>>>(src, dst);
    cudaEventRecord(evCsr, sB);                // CSR ready

    // stream 0: weight split (runs under B's count), then GEMM1 (needs dinv)
    k_splitw<<<64, 256>>>(Wn, w1, w2);
    cudaStreamWaitEvent(0, evDinv, 0);
    k_gemm1g<<<NB_G, 256, G1_SMEM>>>(embed, tokens, Wnh, Wnl, Wb, xh);

    // agg1 (needs CSR)
    cudaStreamWaitEvent(0, evCsr, 0);
    k_agg<<<NB_C, 256>>>(xh, Z);
    // GEMM2: h' = relu(Z @ w1^T + b1) * dinv*256
    k_gemm<D_OUT, true, true, true><<<NB_G, 256, SMEM_DYN>>>(Z, w1h, w1l, b1, hh, nullptr);
    // agg2
    k_agg<<<NB_C, 256>>>(hh, Z);
    // GEMM3: out = Z @ w2^T + b2
    k_gemm<D_OUT, false, false, false><<<NB_G, 256, SMEM_DYN>>>(Z, w2h, w2l, b2, nullptr, out);
}